// round 8
// baseline (speedup 1.0000x reference)
#include <cuda_runtime.h>

// Factorized entropy bottleneck likelihood, elementwise per channel.
// B=16, C=192, H=64, W=64. Layout [B,C,H,W]; each (b,c) plane = 4096 floats.
//
// Fast path: when all tanh(factor) == 0 (true for benchmark inputs: factors
// are zeros), the per-channel 4-layer MLP is affine: L(v) = G*v + H with
// per-channel G>0, H folded from the softplus weight chain. Then
//   lower = G*v + (H - G/2),  upper = lower + G,
//   likelihood = max(|sigmoid(s*up) - sigmoid(s*lo)|, 1e-6), s = sign(lo+up)
// and with ea = e^{-s*up}:
//   |sig(s*up) - sig(s*lo)| = ea*K(s) / ((1+ea)(1+ea*E(s)))
//   E(+1)=e^G, E(-1)=e^{-G}, K(+1)=e^G-1, K(-1)=1-e^{-G}  (per-channel consts)
// -> ONE __expf + ONE __fdividef per element.
// General fallback (any nonzero factor) runs the full MLP from shared memory.

#define NCH 192
#define PLANE 4096        // H*W
#define TPB 256

__device__ __forceinline__ float softplus_f(float x) {
    float ax = fabsf(x);
    return fmaxf(x, 0.0f) + log1pf(__expf(-ax));
}

__device__ __forceinline__ float sigmoid_fast(float z) {
    return __fdividef(1.0f, 1.0f + __expf(-z));
}

struct AffP { float G, Hu, eG, emG, Kp, Km; };

__device__ __forceinline__ float like_affine(float v, const AffP& p) {
    float up = fmaf(p.G, v, p.Hu);
    float su = fmaf(2.0f, up, -p.G);         // lower + upper
    bool pos = su > 0.0f;
    float a  = pos ? up : -up;               // s*up, s = sign(su)
    float ea = __expf(-a);
    float E  = pos ? p.eG : p.emG;
    float K  = pos ? p.Kp : p.Km;
    if (su == 0.0f) K = 0.0f;                // reference: sign=0 -> diff 0 -> clamp
    float eb  = ea * E;                      // e^{-s*lower}
    float den = (1.0f + ea) * (1.0f + eb);
    return fmaxf(__fdividef(ea * K, den), 1e-6f);
}

// Full per-channel MLP, parameters in shared.  sp layout:
//  [0:3)   m0 (softplus)    [3:6)  b0       [6:9)   tanh(f0)
//  [9:18)  m1 (softplus)    [18:21) b1      [21:24) tanh(f1)
//  [24:33) m2 (softplus)    [33:36) b2      [36:39) tanh(f2)
//  [39:42) m3 (softplus)    [42]    b3
__device__ float logits_general(float v, const float* sp) {
    float l[3], t[3];
    #pragma unroll 1
    for (int j = 0; j < 3; j++) l[j] = fmaf(sp[j], v, sp[3 + j]);
    #pragma unroll 1
    for (int j = 0; j < 3; j++) l[j] += sp[6 + j] * tanhf(l[j]);
    #pragma unroll 1
    for (int i = 0; i < 3; i++) {
        float acc = sp[18 + i];
        for (int j = 0; j < 3; j++) acc = fmaf(sp[9 + i * 3 + j], l[j], acc);
        t[i] = acc + sp[21 + i] * tanhf(acc);
    }
    #pragma unroll 1
    for (int i = 0; i < 3; i++) {
        float acc = sp[33 + i];
        for (int j = 0; j < 3; j++) acc = fmaf(sp[24 + i * 3 + j], t[j], acc);
        l[i] = acc + sp[36 + i] * tanhf(acc);
    }
    float acc = sp[42];
    #pragma unroll 1
    for (int j = 0; j < 3; j++) acc = fmaf(sp[39 + j], l[j], acc);
    return acc;
}

__global__ __launch_bounds__(TPB)
void fek_kernel(const float* __restrict__ x,
                const float* __restrict__ m0, const float* __restrict__ b0, const float* __restrict__ f0,
                const float* __restrict__ m1, const float* __restrict__ b1, const float* __restrict__ f1,
                const float* __restrict__ m2, const float* __restrict__ b2, const float* __restrict__ f2,
                const float* __restrict__ m3, const float* __restrict__ b3,
                float* __restrict__ out)
{
    __shared__ float sp[48];
    __shared__ AffP sap;
    __shared__ int s_affine;

    const int plane = blockIdx.x;
    const int c = plane % NCH;
    const int tid = threadIdx.x;

    // Phase 1: derived per-channel params into shared (one value per thread).
    if (tid < 43) {
        float v;
        if      (tid < 3)  v = softplus_f(m0[c * 3 + tid]);
        else if (tid < 6)  v = b0[c * 3 + tid - 3];
        else if (tid < 9)  v = tanhf(f0[c * 3 + tid - 6]);
        else if (tid < 18) v = softplus_f(m1[c * 9 + tid - 9]);
        else if (tid < 21) v = b1[c * 3 + tid - 18];
        else if (tid < 24) v = tanhf(f1[c * 3 + tid - 21]);
        else if (tid < 33) v = softplus_f(m2[c * 9 + tid - 24]);
        else if (tid < 36) v = b2[c * 3 + tid - 33];
        else if (tid < 39) v = tanhf(f2[c * 3 + tid - 36]);
        else if (tid < 42) v = softplus_f(m3[c * 3 + tid - 39]);
        else               v = b3[c];
        sp[tid] = v;
    }
    __syncthreads();

    // Phase 2: fold affine coefficients (thread 0; ~120 flops, amortized over 4096 elems).
    if (tid == 0) {
        bool aff = true;
        #pragma unroll
        for (int j = 0; j < 3; j++)
            aff = aff && (sp[6 + j] == 0.0f) && (sp[21 + j] == 0.0f) && (sp[36 + j] == 0.0f);
        s_affine = aff ? 1 : 0;

        float g0[3], h0[3], g1[3], h1[3], g2[3], h2[3];
        #pragma unroll
        for (int j = 0; j < 3; j++) { g0[j] = sp[j]; h0[j] = sp[3 + j]; }
        #pragma unroll
        for (int i = 0; i < 3; i++) {
            float gg = 0.0f, hh = sp[18 + i];
            #pragma unroll
            for (int j = 0; j < 3; j++) {
                gg = fmaf(sp[9 + i * 3 + j], g0[j], gg);
                hh = fmaf(sp[9 + i * 3 + j], h0[j], hh);
            }
            g1[i] = gg; h1[i] = hh;
        }
        #pragma unroll
        for (int i = 0; i < 3; i++) {
            float gg = 0.0f, hh = sp[33 + i];
            #pragma unroll
            for (int j = 0; j < 3; j++) {
                gg = fmaf(sp[24 + i * 3 + j], g1[j], gg);
                hh = fmaf(sp[24 + i * 3 + j], h1[j], hh);
            }
            g2[i] = gg; h2[i] = hh;
        }
        float G = 0.0f, H = sp[42];
        #pragma unroll
        for (int j = 0; j < 3; j++) {
            G = fmaf(sp[39 + j], g2[j], G);
            H = fmaf(sp[39 + j], h2[j], H);
        }
        sap.G   = G;
        sap.Hu  = fmaf(0.5f, G, H);
        sap.Kp  = expm1f(G);            // e^G - 1   (> 0, G > 0)
        sap.eG  = sap.Kp + 1.0f;        // e^G
        float em = expm1f(-G);          // e^-G - 1
        sap.emG = em + 1.0f;            // e^-G
        sap.Km  = -em;                  // 1 - e^-G  (> 0)
    }
    __syncthreads();

    const float4* __restrict__ xin = (const float4*)(x + (size_t)plane * PLANE);
    float4* __restrict__ o4 = (float4*)(out + (size_t)plane * PLANE);

    if (s_affine) {
        const AffP p = sap;  // to registers
        #pragma unroll
        for (int k = 0; k < PLANE / (4 * TPB); k++) {
            float4 xv = xin[tid + k * TPB];
            float4 r;
            r.x = like_affine(xv.x, p);
            r.y = like_affine(xv.y, p);
            r.z = like_affine(xv.z, p);
            r.w = like_affine(xv.w, p);
            o4[tid + k * TPB] = r;
        }
    } else {
        // General path (not taken for benchmark inputs; correctness fallback).
        #pragma unroll 1
        for (int k = 0; k < PLANE / (4 * TPB); k++) {
            float4 xv = xin[tid + k * TPB];
            float4 r;
            float vv[4] = {xv.x, xv.y, xv.z, xv.w};
            float rr[4];
            #pragma unroll 1
            for (int e = 0; e < 4; e++) {
                float v  = vv[e];
                float lo = logits_general(v - 0.5f, sp);
                float up = logits_general(v + 0.5f, sp);
                float su = lo + up;
                float s  = (su < 0.0f) ? 1.0f : ((su > 0.0f) ? -1.0f : 0.0f);
                float a  = sigmoid_fast(s * up);
                float b  = sigmoid_fast(s * lo);
                rr[e] = fmaxf(fabsf(a - b), 1e-6f);
            }
            r.x = rr[0]; r.y = rr[1]; r.z = rr[2]; r.w = rr[3];
            o4[tid + k * TPB] = r;
        }
    }
}

extern "C" void kernel_launch(void* const* d_in, const int* in_sizes, int n_in,
                              void* d_out, int out_size)
{
    const float* x = (const float*)d_in[0];
    const float *m0, *m1, *m2, *m3, *b0, *b1, *b2, *b3, *f0, *f1, *f2;

    // Disambiguate metadata ordering via in_sizes:
    //   setup_inputs dict order: x, m0,b0,f0, m1,b1,f1, m2,b2,f2, m3,b3
    //     -> in_sizes[2] = bias_0 = 192*3 = 576
    //   reference signature order: x, m0,m1,m2,m3, b0,b1,b2,b3, f0,f1,f2
    //     -> in_sizes[2] = matrix_1 = 192*9 = 1728
    if (in_sizes[2] == 1728) {
        m0 = (const float*)d_in[1];  m1 = (const float*)d_in[2];
        m2 = (const float*)d_in[3];  m3 = (const float*)d_in[4];
        b0 = (const float*)d_in[5];  b1 = (const float*)d_in[6];
        b2 = (const float*)d_in[7];  b3 = (const float*)d_in[8];
        f0 = (const float*)d_in[9];  f1 = (const float*)d_in[10];
        f2 = (const float*)d_in[11];
    } else {
        m0 = (const float*)d_in[1];  b0 = (const float*)d_in[2];  f0 = (const float*)d_in[3];
        m1 = (const float*)d_in[4];  b1 = (const float*)d_in[5];  f1 = (const float*)d_in[6];
        m2 = (const float*)d_in[7];  b2 = (const float*)d_in[8];  f2 = (const float*)d_in[9];
        m3 = (const float*)d_in[10]; b3 = (const float*)d_in[11];
    }

    int planes = out_size / PLANE;  // B*C = 3072
    fek_kernel<<<planes, TPB>>>(x, m0, b0, f0, m1, b1, f1, m2, b2, f2, m3, b3,
                                (float*)d_out);
}

// round 10
// speedup vs baseline: 1.2073x; 1.2073x over previous
#include <cuda_runtime.h>

// Factorized entropy bottleneck likelihood, elementwise per channel.
// B=16, C=192, H=64, W=64. [B,C,H,W]; each (b,c) plane = 4096 floats.
//
// Two kernels:
//  1) fek_prep (192 blocks): per-channel fold of the weight chain into
//     affine params {G, H, e^-G, 1-e^-G, G/2, affine_flag} + raw derived
//     params (for the general fallback), stored in __device__ scratch.
//  2) fek_main (3072 blocks): pure elementwise pass, no shared/syncs.
//     Fast path per element (sign-free algebra; s*lo == |mid| - G/2 for
//     either valid sign orientation, mid = G*v + H):
//       eb  = e^{G/2 - |mid|}            ( = e^{-s*lo} )
//       num = eb * (1 - e^-G)            ( = eb - ea, always >= 0 )
//       den = (1 + eb*e^-G) * (1 + eb)
//       lik = max(num/den, 1e-6)         (mid==0 -> 0 -> clamp, matches ref)

#define NCH 192
#define PLANE 4096
#define TPB 256

__device__ float g_sp[NCH * 48];   // derived per-channel params (general path)
__device__ float g_par[NCH * 8];   // {G, H, emG, Km, flag, G2, -, -}

__device__ __forceinline__ float softplus_f(float x) {
    float ax = fabsf(x);
    return fmaxf(x, 0.0f) + log1pf(__expf(-ax));
}

__device__ __forceinline__ float sigmoid_fast(float z) {
    return __fdividef(1.0f, 1.0f + __expf(-z));
}

// ---------------- prep kernel: one block per channel ----------------
__global__ __launch_bounds__(64)
void fek_prep(const float* __restrict__ m0, const float* __restrict__ b0, const float* __restrict__ f0,
              const float* __restrict__ m1, const float* __restrict__ b1, const float* __restrict__ f1,
              const float* __restrict__ m2, const float* __restrict__ b2, const float* __restrict__ f2,
              const float* __restrict__ m3, const float* __restrict__ b3)
{
    __shared__ float sp[48];
    const int c = blockIdx.x;
    const int tid = threadIdx.x;

    if (tid < 43) {
        float v;
        if      (tid < 3)  v = softplus_f(m0[c * 3 + tid]);
        else if (tid < 6)  v = b0[c * 3 + tid - 3];
        else if (tid < 9)  v = tanhf(f0[c * 3 + tid - 6]);
        else if (tid < 18) v = softplus_f(m1[c * 9 + tid - 9]);
        else if (tid < 21) v = b1[c * 3 + tid - 18];
        else if (tid < 24) v = tanhf(f1[c * 3 + tid - 21]);
        else if (tid < 33) v = softplus_f(m2[c * 9 + tid - 24]);
        else if (tid < 36) v = b2[c * 3 + tid - 33];
        else if (tid < 39) v = tanhf(f2[c * 3 + tid - 36]);
        else if (tid < 42) v = softplus_f(m3[c * 3 + tid - 39]);
        else               v = b3[c];
        sp[tid] = v;
        g_sp[c * 48 + tid] = v;
    }
    __syncthreads();

    if (tid == 0) {
        bool aff = true;
        #pragma unroll
        for (int j = 0; j < 3; j++)
            aff = aff && (sp[6 + j] == 0.0f) && (sp[21 + j] == 0.0f) && (sp[36 + j] == 0.0f);

        float g0[3], h0[3], g1[3], h1[3], g2[3], h2[3];
        #pragma unroll
        for (int j = 0; j < 3; j++) { g0[j] = sp[j]; h0[j] = sp[3 + j]; }
        #pragma unroll
        for (int i = 0; i < 3; i++) {
            float gg = 0.0f, hh = sp[18 + i];
            #pragma unroll
            for (int j = 0; j < 3; j++) {
                gg = fmaf(sp[9 + i * 3 + j], g0[j], gg);
                hh = fmaf(sp[9 + i * 3 + j], h0[j], hh);
            }
            g1[i] = gg; h1[i] = hh;
        }
        #pragma unroll
        for (int i = 0; i < 3; i++) {
            float gg = 0.0f, hh = sp[33 + i];
            #pragma unroll
            for (int j = 0; j < 3; j++) {
                gg = fmaf(sp[24 + i * 3 + j], g1[j], gg);
                hh = fmaf(sp[24 + i * 3 + j], h1[j], hh);
            }
            g2[i] = gg; h2[i] = hh;
        }
        float G = 0.0f, H = sp[42];
        #pragma unroll
        for (int j = 0; j < 3; j++) {
            G = fmaf(sp[39 + j], g2[j], G);
            H = fmaf(sp[39 + j], h2[j], H);
        }
        float em = expm1f(-G);            // e^-G - 1
        g_par[c * 8 + 0] = G;
        g_par[c * 8 + 1] = H;
        g_par[c * 8 + 2] = em + 1.0f;     // e^-G
        g_par[c * 8 + 3] = -em;           // 1 - e^-G  (>0 since G>0)
        g_par[c * 8 + 4] = aff ? 1.0f : 0.0f;
        g_par[c * 8 + 5] = 0.5f * G;
        g_par[c * 8 + 6] = 0.0f;
        g_par[c * 8 + 7] = 0.0f;
    }
}

// ---------------- general fallback MLP (reads params from global) ----------------
__device__ float logits_general(float v, const float* sp) {
    float l[3], t[3];
    #pragma unroll 1
    for (int j = 0; j < 3; j++) l[j] = fmaf(sp[j], v, sp[3 + j]);
    #pragma unroll 1
    for (int j = 0; j < 3; j++) l[j] += sp[6 + j] * tanhf(l[j]);
    #pragma unroll 1
    for (int i = 0; i < 3; i++) {
        float acc = sp[18 + i];
        for (int j = 0; j < 3; j++) acc = fmaf(sp[9 + i * 3 + j], l[j], acc);
        t[i] = acc + sp[21 + i] * tanhf(acc);
    }
    #pragma unroll 1
    for (int i = 0; i < 3; i++) {
        float acc = sp[33 + i];
        for (int j = 0; j < 3; j++) acc = fmaf(sp[24 + i * 3 + j], t[j], acc);
        l[i] = acc + sp[36 + i] * tanhf(acc);
    }
    float acc = sp[42];
    #pragma unroll 1
    for (int j = 0; j < 3; j++) acc = fmaf(sp[39 + j], l[j], acc);
    return acc;
}

// ---------------- main kernel: one block per (b,c) plane ----------------
__global__ __launch_bounds__(TPB)
void fek_main(const float* __restrict__ x, float* __restrict__ out)
{
    const int plane = blockIdx.x;
    const int c = plane % NCH;
    const int tid = threadIdx.x;

    const float* pp = g_par + c * 8;
    const float G    = pp[0];
    const float H    = pp[1];
    const float emG  = pp[2];
    const float Km   = pp[3];
    const float flag = pp[4];
    const float G2   = pp[5];

    const float4* __restrict__ xin = (const float4*)(x + (size_t)plane * PLANE);
    float4* __restrict__ o4 = (float4*)(out + (size_t)plane * PLANE);

    if (flag != 0.0f) {
        #pragma unroll
        for (int k = 0; k < PLANE / (4 * TPB); k++) {
            float4 xv = xin[tid + k * TPB];
            float4 r;
            #pragma unroll
            for (int e = 0; e < 4; e++) {
                float v   = (&xv.x)[e];
                float mid = fmaf(G, v, H);                 // (lower+upper)/2
                float eb  = __expf(G2 - fabsf(mid));       // e^{-s*lower}
                float ea  = eb * emG;                      // e^{-s*upper}
                float num = eb * Km;                       // eb - ea  (>= 0)
                if (mid == 0.0f) num = 0.0f;               // ref sign=0 clamp
                float den = (1.0f + ea) * (1.0f + eb);
                (&r.x)[e] = fmaxf(__fdividef(num, den), 1e-6f);
            }
            o4[tid + k * TPB] = r;
        }
    } else {
        // General path (benchmark never takes it; exact fallback).
        const float* sp = g_sp + c * 48;
        #pragma unroll 1
        for (int k = 0; k < PLANE / (4 * TPB); k++) {
            float4 xv = xin[tid + k * TPB];
            float4 r;
            #pragma unroll 1
            for (int e = 0; e < 4; e++) {
                float v  = (&xv.x)[e];
                float lo = logits_general(v - 0.5f, sp);
                float up = logits_general(v + 0.5f, sp);
                float su = lo + up;
                float s  = (su < 0.0f) ? 1.0f : ((su > 0.0f) ? -1.0f : 0.0f);
                float a  = sigmoid_fast(s * up);
                float b  = sigmoid_fast(s * lo);
                (&r.x)[e] = fmaxf(fabsf(a - b), 1e-6f);
            }
            o4[tid + k * TPB] = r;
        }
    }
}

extern "C" void kernel_launch(void* const* d_in, const int* in_sizes, int n_in,
                              void* d_out, int out_size)
{
    const float* x = (const float*)d_in[0];
    const float *m0, *m1, *m2, *m3, *b0, *b1, *b2, *b3, *f0, *f1, *f2;

    // Disambiguate metadata ordering via in_sizes:
    //   dict order:      x, m0,b0,f0, m1,b1,f1, m2,b2,f2, m3,b3  -> in_sizes[2]=576
    //   signature order: x, m0..m3, b0..b3, f0..f2               -> in_sizes[2]=1728
    if (in_sizes[2] == 1728) {
        m0 = (const float*)d_in[1];  m1 = (const float*)d_in[2];
        m2 = (const float*)d_in[3];  m3 = (const float*)d_in[4];
        b0 = (const float*)d_in[5];  b1 = (const float*)d_in[6];
        b2 = (const float*)d_in[7];  b3 = (const float*)d_in[8];
        f0 = (const float*)d_in[9];  f1 = (const float*)d_in[10];
        f2 = (const float*)d_in[11];
    } else {
        m0 = (const float*)d_in[1];  b0 = (const float*)d_in[2];  f0 = (const float*)d_in[3];
        m1 = (const float*)d_in[4];  b1 = (const float*)d_in[5];  f1 = (const float*)d_in[6];
        m2 = (const float*)d_in[7];  b2 = (const float*)d_in[8];  f2 = (const float*)d_in[9];
        m3 = (const float*)d_in[10]; b3 = (const float*)d_in[11];
    }

    fek_prep<<<NCH, 64>>>(m0, b0, f0, m1, b1, f1, m2, b2, f2, m3, b3);

    int planes = out_size / PLANE;  // B*C = 3072
    fek_main<<<planes, TPB>>>(x, (float*)d_out);
}